// round 9
// baseline (speedup 1.0000x reference)
#include <cuda_runtime.h>
#include <cstdint>
#include <cstring>

#define NS    32768
#define NBITS 64
#define MG    8
#define HID   256
#define NC    100

typedef unsigned long long ull;

// ---------------------------------------------------------------------------
// Threefry-2x32, 20 rounds — bit-exact match of JAX's threefry2x32 primitive.
// ---------------------------------------------------------------------------
__host__ __device__ __forceinline__ void threefry2x32(
    uint32_t k0, uint32_t k1, uint32_t c0, uint32_t c1,
    uint32_t& o0, uint32_t& o1) {
  uint32_t ks2 = k0 ^ k1 ^ 0x1BD11BDAu;
  uint32_t x0 = c0 + k0;
  uint32_t x1 = c1 + k1;
#define TF_RND(r) { x0 += x1; x1 = (x1 << (r)) | (x1 >> (32 - (r))); x1 ^= x0; }
  TF_RND(13) TF_RND(15) TF_RND(26) TF_RND(6)
  x0 += k1;  x1 += ks2 + 1u;
  TF_RND(17) TF_RND(29) TF_RND(16) TF_RND(24)
  x0 += ks2; x1 += k0 + 2u;
  TF_RND(13) TF_RND(15) TF_RND(26) TF_RND(6)
  x0 += k0;  x1 += k1 + 3u;
  TF_RND(17) TF_RND(29) TF_RND(16) TF_RND(24)
  x0 += k1;  x1 += ks2 + 4u;
  TF_RND(13) TF_RND(15) TF_RND(26) TF_RND(6)
  x0 += ks2; x1 += k0 + 5u;
#undef TF_RND
  o0 = x0; o1 = x1;
}

// ---------------------------------------------------------------------------
// Device-global scratch
// ---------------------------------------------------------------------------
__device__ float g_xp  [NS * NBITS];
__device__ float g_xmap[NS * NBITS];
__device__ unsigned char g_target[NS * MG];
__device__ unsigned int  g_xbits[NS * 2];
__device__ int           g_K[NS];
__device__ unsigned char g_act[NS * NC];
__device__ unsigned char g_ct[NC * MG];
__device__ unsigned int  g_cbits[NC * 2];
__device__ double g_mapSum;
__device__ double g_netSum;
__device__ unsigned long long g_hits;
__device__ unsigned long long g_hamSum;
__device__ unsigned long long g_actTot;
__device__ int g_tmode;

__device__ __forceinline__ bool read_tpl(const void* p, int b) {
  if (g_tmode == 0) return ((const unsigned char*)p)[b] != 0;
  return ((const int*)p)[b] != 0;
}

// ---------------------------------------------------------------------------
// Kernel 1 (merged): accumulator init + template dtype detect + centroid prep
// ---------------------------------------------------------------------------
__global__ void setup_kernel(const float* __restrict__ cen,
                             const int* __restrict__ perm,
                             const unsigned char* tm, const unsigned char* tr) {
  __shared__ int permS[NBITS];
  int t = threadIdx.x;
  if (t < NBITS) permS[t] = perm[t];
  if (t == 0) {
    g_mapSum = 0.0; g_netSum = 0.0;
    g_hits = 0ull; g_hamSum = 0ull; g_actTot = 0ull;
    int has3F = 0, mis = 0;
    for (int i = 0; i < 64; i++) {
      unsigned char bm = tm[i], br = tr[i];
      if (bm == 0x3F || br == 0x3F) has3F = 1;
      if (i & 3) mis += (bm != 0) + (br != 0);
    }
    g_tmode = has3F ? 1 : (mis ? 0 : 1);
  }
  __syncthreads();
  if (t >= NC) return;
  unsigned int w0 = 0, w1 = 0;
  for (int b = 0; b < NBITS; b++) {
    bool bit = cen[t * NBITS + permS[b]] > 0.f;
    if (bit) { if (b < 32) w0 |= 1u << b; else w1 |= 1u << (b - 32); }
  }
  g_cbits[t * 2 + 0] = w0;
  g_cbits[t * 2 + 1] = w1;
  for (int m = 0; m < MG; m++) {
    unsigned int w = (m < 4) ? w0 : w1;
    g_ct[t * MG + m] = (unsigned char)((w >> ((m & 3) * 8)) & 0xffu);
  }
}

// ---------------------------------------------------------------------------
// Kernel 2: PRNG draws, stable argsort ranks, flips, targets, sign bits.
// ---------------------------------------------------------------------------
__global__ void prep_kernel(const float* __restrict__ x,
                            const int* __restrict__ perm,
                            const void* tmap, const void* traw,
                            uint32_t km0, uint32_t km1,
                            uint32_t kr0, uint32_t kr1) {
  __shared__ float xps[2][NBITS];
  __shared__ unsigned int us[2][2][NBITS];
  __shared__ int permS[NBITS];
  __shared__ int tposS[2][4];
  __shared__ int ranksS[2][2][4];
  __shared__ unsigned int rawb[2][2];
  __shared__ unsigned int xbw[2][2];

  int tid = threadIdx.x;
  if (tid < NBITS) permS[tid] = perm[tid];
  if (tid < 2) {
    const void* tp = (tid == 0) ? tmap : traw;
    int c = 0;
    for (int b = 0; b < NBITS; b++)
      if (read_tpl(tp, b)) { if (c < 4) tposS[tid][c] = b; c++; }
  }
  if (tid < 4) { rawb[tid >> 1][tid & 1] = 0u; xbw[tid >> 1][tid & 1] = 0u; }
  __syncthreads();

  int rid = tid >> 7;
  int sub = tid & 127;
  int op  = sub >> 6;
  int b   = sub & 63;
  int row = blockIdx.x * 2 + rid;

  if (op == 0) xps[rid][b] = x[row * NBITS + permS[b]];
  uint32_t k0 = op ? kr0 : km0;
  uint32_t k1 = op ? kr1 : km1;
  uint32_t o0, o1;
  threefry2x32(k0, k1, 0u, (uint32_t)(row * NBITS + b), o0, o1);
  us[rid][op][b] = (o0 ^ o1) >> 9;
  __syncthreads();

  if (b < 4) {
    int tpos = tposS[op][b];
    unsigned int ut = us[rid][op][tpos];
    int cnt = 0;
    for (int j = 0; j < NBITS; j++) {
      unsigned int uj = us[rid][op][j];
      cnt += (uj < ut) || (uj == ut && j < tpos);
    }
    ranksS[rid][op][b] = cnt;
  }
  __syncthreads();

  float v = xps[rid][b];
  bool flip = (b == ranksS[rid][op][0]) | (b == ranksS[rid][op][1]) |
              (b == ranksS[rid][op][2]) | (b == ranksS[rid][op][3]);
  if (op == 0) {
    g_xp  [row * NBITS + b] = v;
    g_xmap[row * NBITS + b] = flip ? -v : v;
    if (v > 0.f) atomicOr(&xbw[rid][b >> 5], 1u << (b & 31));
  } else {
    bool bit = flip ? (v < 0.f) : (v > 0.f);
    if (bit) atomicOr(&rawb[rid][b >> 5], 1u << (b & 31));
  }
  __syncthreads();

  if (op == 1 && b < MG) {
    unsigned int w = rawb[rid][b >> 2];
    g_target[row * MG + b] = (unsigned char)((w >> ((b & 3) * 8)) & 0xffu);
  }
  if (op == 0 && b < 2) g_xbits[row * 2 + b] = xbw[rid][b];
}

// ---------------------------------------------------------------------------
// Kernel 3: active-class compaction + exact hamming sums. 1 warp / row.
// ---------------------------------------------------------------------------
__global__ void ham_kernel(const int* __restrict__ y) {
  int tid = threadIdx.x, w = tid >> 5, l = tid & 31;
  int row = blockIdx.x * 8 + w;
  unsigned int xb0 = g_xbits[row * 2], xb1 = g_xbits[row * 2 + 1];
  int K = 0;
  unsigned long long hs = 0ull;
  for (int cb = 0; cb < 128; cb += 32) {
    int c = cb + l;
    bool act = (c < NC) && (y[row * NC + c] > 0);
    unsigned int msk = __ballot_sync(0xffffffffu, act);
    if (act) {
      int pos = K + __popc(msk & ((1u << l) - 1u));
      g_act[row * NC + pos] = (unsigned char)c;
      hs += (unsigned long long)(__popc(xb0 ^ g_cbits[c * 2]) +
                                 __popc(xb1 ^ g_cbits[c * 2 + 1]));
    }
    K += __popc(msk);
  }
  if (l == 0) g_K[row] = K;
  for (int o = 16; o; o >>= 1)
    hs += __shfl_xor_sync(0xffffffffu, hs, o);
  if (l == 0) {
    atomicAdd(&g_hamSum, hs);
    atomicAdd(&g_actTot, (unsigned long long)K);
  }
}

// ---------------------------------------------------------------------------
// Kernel 4: fused batched MLP + losses. FFMA2, W2 streamed via pipelined LDG.
//
// CTA: 256 thr = 8 warps; 64 rows. Warp w: rg = w>>1 (rows [16rg,16rg+16)),
//   cg = w&1 (cols [128cg,+128)); lane l owns cols 128cg+4l..+3.
// W2 read DIRECTLY from global (L1/L2): 1 coalesced LDG.128 per warp-k,
//   software-pipelined 4 k-rows ahead in registers (covers L2 latency).
// hT [k][row] stride 68: broadcast LDS128 row-quads -> natural f32x2 pairs.
// Only 5 __syncthreads per m (was 36). No cp.async, no smem W staging.
// smem 78KB -> 2 CTAs/SM (reg-limited at 128 regs).
// ---------------------------------------------------------------------------
#define HSTRIDE  68
#define LSTRIDE  264
#define SM_W1S   0          // 2048 floats
#define SM_B1    2048       // 256
#define SM_B2    2304       // 256
#define SM_HT    2560       // 17408 (256 k * 68); logits alias (64 * 264)
#define SM_FLOATS 19968     // 79872 bytes

__device__ __forceinline__ void ffma2(ull& d, ull a, ull b) {
  asm("fma.rn.f32x2 %0, %1, %2, %0;" : "+l"(d) : "l"(a), "l"(b));
}
__device__ __forceinline__ ull dup2(float v) {
  ull r;
  asm("mov.b64 %0, {%1, %1};" : "=l"(r) : "f"(v));
  return r;
}
__device__ __forceinline__ float2 unpack2(ull v) {
  float2 t;
  asm("mov.b64 {%0, %1}, %2;" : "=f"(t.x), "=f"(t.y) : "l"(v));
  return t;
}
__device__ __forceinline__ float fast_rcp(float d) {
  float r = __uint_as_float(0x7EF311C3u - __float_as_uint(d));
  r = r * (2.0f - d * r);
  r = r * (2.0f - d * r);
  r = r * (2.0f - d * r);
  return r;
}

__global__ void __launch_bounds__(256, 2)
mlp_kernel(const float* __restrict__ W1, const float* __restrict__ b1,
           const float* __restrict__ W2, const float* __restrict__ b2) {
  extern __shared__ float sm[];
  float* W1s    = sm + SM_W1S;
  float* b1s    = sm + SM_B1;
  float* b2s    = sm + SM_B2;
  float* hT     = sm + SM_HT;
  float* logits = sm + SM_HT;   // alias: hT dead after GEMM2 each m

  int tid = threadIdx.x, w = tid >> 5, l = tid & 31;
  int rg = w >> 1, cg = w & 1;
  int pass = blockIdx.y;
  int row0 = blockIdx.x * 64;
  const float* inp = (pass == 0) ? g_xmap : g_xp;

  double mapAcc = 0.0, netAcc = 0.0;
  unsigned int hitAcc = 0;

  for (int mm = 0; mm < MG; mm++) {
    __syncthreads();   // (1) prev logits reads done before hT/W1s overwrite
    {
      const float4* w1p = (const float4*)(W1 + mm * 2048);
      float4* w1d = (float4*)W1s;
      w1d[tid] = w1p[tid];
      w1d[tid + 256] = w1p[tid + 256];
      b1s[tid] = b1[mm * 256 + tid];
      b2s[tid] = b2[mm * 256 + tid];
    }
    __syncthreads();   // (2)

    // ---- GEMM1: h = silu(xs @ W1 + b1) -> hT[k][row], stride 68 ----
    {
      // lane l holds row 8w+(l>>2), cols mm*8 + 2(l&3), +1
      float2 xr = *(const float2*)(inp + (row0 + 8 * w + (l >> 2)) * NBITS +
                                   mm * 8 + 2 * (l & 3));
      float xv[8][8];
#pragma unroll
      for (int i = 0; i < 8; i++)
#pragma unroll
        for (int s = 0; s < 8; s++)
          xv[i][s] = __shfl_sync(0xffffffffu, (s & 1) ? xr.y : xr.x,
                                 4 * i + (s >> 1));
#pragma unroll
      for (int kk = 0; kk < 8; kk++) {
        int k = kk * 32 + l;
        float w1c[8];
#pragma unroll
        for (int s = 0; s < 8; s++) w1c[s] = W1s[s * 256 + k];
        float bk = b1s[k];
        float* hp = hT + k * HSTRIDE + 8 * w;
#pragma unroll
        for (int ip = 0; ip < 4; ip++) {
          float h2[2];
#pragma unroll
          for (int u = 0; u < 2; u++) {
            int i = 2 * ip + u;
            float a = bk;
#pragma unroll
            for (int s = 0; s < 8; s++) a = fmaf(xv[i][s], w1c[s], a);
            float t = __expf(-a);
            float d = 1.0f + fminf(t, 1e30f);
            h2[u] = a * fast_rcp(d);
          }
          *(float2*)(hp + 2 * ip) = make_float2(h2[0], h2[1]);
        }
      }
    }
    __syncthreads();   // (3) hT complete before cross-warp GEMM2 reads

    // ---- GEMM2: 16 rows x 128 cols per warp; W2 via pipelined LDG ----
    ull acc2[8][4];
#pragma unroll
    for (int i = 0; i < 8; i++)
#pragma unroll
      for (int j = 0; j < 4; j++) acc2[i][j] = 0ull;

    const float* wg = W2 + mm * 65536 + 128 * cg + 4 * l;
    float4 wb[4];
#pragma unroll
    for (int j = 0; j < 4; j++) wb[j] = *(const float4*)(wg + j * 256);

#define G2_BODY(KB, PREFETCH)                                              \
    {                                                                      \
      const float* hk0 = hT + (KB) * 4 * HSTRIDE + 16 * rg;                \
      _Pragma("unroll")                                                    \
      for (int j = 0; j < 4; j++) {                                        \
        float4 wv = wb[j];                                                 \
        if (PREFETCH)                                                      \
          wb[j] = *(const float4*)(wg + ((KB) * 4 + 4 + j) * 256);         \
        ull wd0 = dup2(wv.x), wd1 = dup2(wv.y);                            \
        ull wd2 = dup2(wv.z), wd3 = dup2(wv.w);                            \
        const float* hk = hk0 + j * HSTRIDE;                               \
        _Pragma("unroll")                                                  \
        for (int jj = 0; jj < 4; jj++) {                                   \
          ulonglong2 hp = *(const ulonglong2*)(hk + 4 * jj);               \
          ffma2(acc2[2 * jj][0],     hp.x, wd0);                           \
          ffma2(acc2[2 * jj][1],     hp.x, wd1);                           \
          ffma2(acc2[2 * jj][2],     hp.x, wd2);                           \
          ffma2(acc2[2 * jj][3],     hp.x, wd3);                           \
          ffma2(acc2[2 * jj + 1][0], hp.y, wd0);                           \
          ffma2(acc2[2 * jj + 1][1], hp.y, wd1);                           \
          ffma2(acc2[2 * jj + 1][2], hp.y, wd2);                           \
          ffma2(acc2[2 * jj + 1][3], hp.y, wd3);                           \
        }                                                                  \
      }                                                                    \
    }

    for (int kb = 0; kb < 63; kb++) G2_BODY(kb, 1)
    G2_BODY(63, 0)
#undef G2_BODY

    __syncthreads();   // (4) all hT reads done before logits overwrite

    // ---- epilogue: logits (+bias) to smem, then per-row reductions ----
    {
      float4 bA = *(const float4*)(b2s + 128 * cg + 4 * l);
      float* lbase = logits + 128 * cg + 4 * l;
#pragma unroll
      for (int rp = 0; rp < 8; rp++) {
        float2 t0 = unpack2(acc2[rp][0]);
        float2 t1 = unpack2(acc2[rp][1]);
        float2 t2 = unpack2(acc2[rp][2]);
        float2 t3 = unpack2(acc2[rp][3]);
        int r0 = 16 * rg + 2 * rp;
        *(float4*)(lbase + r0 * LSTRIDE) =
            make_float4(t0.x + bA.x, t1.x + bA.y, t2.x + bA.z, t3.x + bA.w);
        *(float4*)(lbase + (r0 + 1) * LSTRIDE) =
            make_float4(t0.y + bA.x, t1.y + bA.y, t2.y + bA.z, t3.y + bA.w);
      }
    }
    __syncthreads();   // (5)

    for (int i = 0; i < 8; i++) {
      int lrow = w * 8 + i;
      int grow = row0 + lrow;
      float v[8];
      {
        float4 va = *(const float4*)(logits + lrow * LSTRIDE + 8 * l);
        float4 vb = *(const float4*)(logits + lrow * LSTRIDE + 8 * l + 4);
        v[0] = va.x; v[1] = va.y; v[2] = va.z; v[3] = va.w;
        v[4] = vb.x; v[5] = vb.y; v[6] = vb.z; v[7] = vb.w;
      }
      float mx = v[0]; int ai = 8 * l;
#pragma unroll
      for (int j = 1; j < 8; j++)
        if (v[j] > mx) { mx = v[j]; ai = 8 * l + j; }
      for (int o = 16; o; o >>= 1) {
        float vm = __shfl_xor_sync(0xffffffffu, mx, o);
        int   vi = __shfl_xor_sync(0xffffffffu, ai, o);
        if (vm > mx || (vm == mx && vi < ai)) { mx = vm; ai = vi; }
      }
      float se = 0.f;
#pragma unroll
      for (int j = 0; j < 8; j++) se += __expf(v[j] - mx);
      for (int o = 16; o; o >>= 1)
        se += __shfl_xor_sync(0xffffffffu, se, o);
      float lse = mx + __logf(se);
      __syncwarp();

      if (pass == 0) {
        if (l == 0) {
          int tgt = g_target[grow * MG + mm];
          mapAcc += (double)(lse - logits[lrow * LSTRIDE + tgt]);
          hitAcc += (ai == tgt) ? 1u : 0u;
        }
      } else {
        int K = g_K[grow];
        const unsigned char* al = g_act + grow * NC;
        double gs = 0.0;
        for (int ci = l; ci < K; ci += 32)
          gs += (double)logits[lrow * LSTRIDE + g_ct[al[ci] * MG + mm]];
        for (int o = 16; o; o >>= 1)
          gs += __shfl_xor_sync(0xffffffffu, gs, o);
        if (l == 0) netAcc += (double)lse - gs / (double)K;
      }
      __syncwarp();
    }
  }

  if (l == 0) {
    if (pass == 0) {
      atomicAdd(&g_mapSum, mapAcc);
      atomicAdd(&g_hits, (unsigned long long)hitAcc);
    } else {
      atomicAdd(&g_netSum, netAcc);
    }
  }
}

// ---------------------------------------------------------------------------
// Kernel 5: finalize 5 scalars
// ---------------------------------------------------------------------------
__global__ void finalize_kernel(float* out) {
  if (threadIdx.x == 0) {
    double net = g_netSum / (double)NS;
    double map = g_mapSum / (double)NS;
    out[0] = (float)(net + map);
    out[1] = (float)net;
    out[2] = (float)map;
    out[3] = (float)((double)g_hits / ((double)NS * (double)MG));
    out[4] = (float)((double)g_hamSum / (double)g_actTot);
  }
}

// ---------------------------------------------------------------------------
extern "C" void kernel_launch(void* const* d_in, const int* in_sizes, int n_in,
                              void* d_out, int out_size) {
  const float* x    = (const float*)d_in[0];
  const int*   y    = (const int*)  d_in[1];
  const float* cen  = (const float*)d_in[2];
  const int*   perm = (const int*)  d_in[3];
  const void*  tmap = d_in[4];
  const void*  traw = d_in[5];
  const float* W1   = (const float*)d_in[6];
  const float* b1   = (const float*)d_in[7];
  const float* W2   = (const float*)d_in[8];
  const float* b2   = (const float*)d_in[9];
  float* out = (float*)d_out;

  uint32_t km0, km1, kr0, kr1;
  threefry2x32(0u, 1u, 0u, 0u, km0, km1);
  threefry2x32(0u, 1u, 0u, 1u, kr0, kr1);

  cudaFuncSetAttribute(mlp_kernel, cudaFuncAttributeMaxDynamicSharedMemorySize,
                       SM_FLOATS * 4);

  setup_kernel<<<1, 128>>>(cen, perm, (const unsigned char*)tmap,
                           (const unsigned char*)traw);
  prep_kernel<<<NS / 2, 256>>>(x, perm, tmap, traw, km0, km1, kr0, kr1);
  ham_kernel<<<NS / 8, 256>>>(y);
  dim3 grid(NS / 64, 2);
  mlp_kernel<<<grid, 256, SM_FLOATS * 4>>>(W1, b1, W2, b2);
  finalize_kernel<<<1, 32>>>(out);
  (void)in_sizes; (void)n_in; (void)out_size;
}